// round 7
// baseline (speedup 1.0000x reference)
#include <cuda_runtime.h>

// ---------------------------------------------------------------------------
// FiSHAttention — fp32 baseline (round 7 resubmit; R1-R6 never ran: broker
// GPUAcquisitionTimeout every round — this source is still unmeasured)
//   K1: fused GEMM  y = x @ [w_qkv(q,k rows 0:512); w_v]^T  -> QS,KS,VS scatter
//   K2: fused flash attention, S[k]=QK^T shared across 12 heads,
//       softmax WITHOUT max-subtraction (logits provably tiny), PV accumulate
//   K3: GEMM out = AO @ w_proj^T + b_proj
// ---------------------------------------------------------------------------

constexpr int BATCH = 8;
constexpr int SEQ   = 1024;
constexpr int DIMS  = 768;
constexpr int NH    = 12;   // local heads
constexpr int NG    = 4;    // global heads
constexpr int HD    = 64;   // head dim
constexpr int TOK   = BATCH * SEQ;          // 8192

// scratch (static device memory — no allocations allowed)
__device__ float g_QS[BATCH * NG * SEQ * HD];   // (b,k,n,d) scaled by 1/8
__device__ float g_KS[BATCH * NG * SEQ * HD];   // (b,k,n,d)
__device__ float g_VS[BATCH * NH * SEQ * HD];   // (b,h,n,d)
__device__ float g_AO[TOK * DIMS];              // (token, h*64+d)

// ---------------------------------------------------------------------------
// Tiled SGEMM: C[M x NC] = A[M x 768] @ B[NC x 768]^T
// BM=BN=128, BK=8, 256 threads, 8x8 micro-tile (split 4+4 to avoid conflicts)
// EPI==0: A=x, B=cat(w_qkv[0:512], w_v), scatter into QS/KS/VS
// EPI==1: A=g_AO, B=w_proj, C=out + bias
// ---------------------------------------------------------------------------
template <int EPI>
__global__ __launch_bounds__(256, 2) void k_sgemm(
    const float* __restrict__ A,
    const float* __restrict__ B0,
    const float* __restrict__ B1,
    const float* __restrict__ bias,
    float* __restrict__ Cout)
{
    __shared__ float As[8][128];
    __shared__ float Bs[8][128];

    const int t  = threadIdx.x;
    const int bm = blockIdx.x;
    const int bn = blockIdx.y;
    const int tx = t & 15;
    const int ty = t >> 4;
    const int lr = t >> 1;          // 0..127 row within tile
    const int lc = (t & 1) << 2;    // 0 or 4 (k offset)

    const float* Ap   = (EPI == 1) ? (const float*)g_AO : A;
    const float* Arow = Ap + (bm * 128 + lr) * DIMS + lc;
    const int    ncol = bn * 128 + lr;
    const float* Brow;
    if (EPI == 0)
        Brow = (ncol < 512) ? (B0 + ncol * DIMS + lc)
                            : (B1 + (ncol - 512) * DIMS + lc);
    else
        Brow = B0 + ncol * DIMS + lc;

    float acc[8][8];
#pragma unroll
    for (int i = 0; i < 8; i++)
#pragma unroll
        for (int j = 0; j < 8; j++) acc[i][j] = 0.f;

    for (int kt = 0; kt < DIMS; kt += 8) {
        float4 av = *reinterpret_cast<const float4*>(Arow + kt);
        float4 bv = *reinterpret_cast<const float4*>(Brow + kt);
        __syncthreads();
        As[lc + 0][lr] = av.x; As[lc + 1][lr] = av.y;
        As[lc + 2][lr] = av.z; As[lc + 3][lr] = av.w;
        Bs[lc + 0][lr] = bv.x; Bs[lc + 1][lr] = bv.y;
        Bs[lc + 2][lr] = bv.z; Bs[lc + 3][lr] = bv.w;
        __syncthreads();
#pragma unroll
        for (int kk = 0; kk < 8; kk++) {
            float a[8], bb[8];
            *reinterpret_cast<float4*>(&a[0])  = *reinterpret_cast<const float4*>(&As[kk][ty * 4]);
            *reinterpret_cast<float4*>(&a[4])  = *reinterpret_cast<const float4*>(&As[kk][64 + ty * 4]);
            *reinterpret_cast<float4*>(&bb[0]) = *reinterpret_cast<const float4*>(&Bs[kk][tx * 4]);
            *reinterpret_cast<float4*>(&bb[4]) = *reinterpret_cast<const float4*>(&Bs[kk][64 + tx * 4]);
#pragma unroll
            for (int i = 0; i < 8; i++)
#pragma unroll
                for (int j = 0; j < 8; j++)
                    acc[i][j] = fmaf(a[i], bb[j], acc[i][j]);
        }
    }

    // epilogue: rows {ih*64+ty*4+ii}, cols {jh*64+tx*4 .. +3} (float4-contiguous)
#pragma unroll
    for (int ih = 0; ih < 2; ih++)
#pragma unroll
        for (int ii = 0; ii < 4; ii++) {
            int m    = bm * 128 + ih * 64 + ty * 4 + ii;
            int bidx = m >> 10;
            int n    = m & 1023;
#pragma unroll
            for (int jh = 0; jh < 2; jh++) {
                int    c0 = bn * 128 + jh * 64 + tx * 4;
                float4 v  = make_float4(acc[ih * 4 + ii][jh * 4 + 0],
                                        acc[ih * 4 + ii][jh * 4 + 1],
                                        acc[ih * 4 + ii][jh * 4 + 2],
                                        acc[ih * 4 + ii][jh * 4 + 3]);
                if (EPI == 0) {
                    int d = c0 & 63;
                    if (c0 < 256) {
                        int k = c0 >> 6;
                        v.x *= 0.125f; v.y *= 0.125f; v.z *= 0.125f; v.w *= 0.125f;
                        *reinterpret_cast<float4*>(
                            &g_QS[(((bidx * NG + k) << 10) + n) * HD + d]) = v;
                    } else if (c0 < 512) {
                        int k = (c0 - 256) >> 6;
                        *reinterpret_cast<float4*>(
                            &g_KS[(((bidx * NG + k) << 10) + n) * HD + d]) = v;
                    } else {
                        int h = (c0 - 512) >> 6;
                        *reinterpret_cast<float4*>(
                            &g_VS[(((bidx * NH + h) << 10) + n) * HD + d]) = v;
                    }
                } else {
                    float4 b4 = *reinterpret_cast<const float4*>(&bias[c0]);
                    v.x += b4.x; v.y += b4.y; v.z += b4.z; v.w += b4.w;
                    *reinterpret_cast<float4*>(&Cout[m * DIMS + c0]) = v;
                }
            }
        }
}

// ---------------------------------------------------------------------------
// Fused flash attention.
// grid = (32 i-tiles, 8 batches), 256 threads, TM=TN=32.
// Per j-tile: S[k][32][32] computed once, mixed per head (groups of 4),
// exp (no max subtraction — logits are tiny), PV accumulated into smem O.
// smem: QiT 32K | KV(K^T then V) 32K | S 16.5K | E 16.5K | O 96K | misc
// ---------------------------------------------------------------------------
constexpr int SM_QIT  = 0;
constexpr int SM_KV   = SM_QIT + 4 * 64 * 32;      // 8192
constexpr int SM_S    = SM_KV + 4 * 64 * 32;       // 16384
constexpr int SM_E    = SM_S + 4 * 32 * 33;        // 20608
constexpr int SM_O    = SM_E + 4 * 32 * 33;        // 24832
constexpr int SM_DEN  = SM_O + 12 * 32 * 64;       // 49408
constexpr int SM_DRED = SM_DEN + 12 * 32;          // 49792
constexpr int SM_MIX  = SM_DRED + 256;             // 50048
constexpr int SM_TOT  = SM_MIX + 48;               // 50096 floats = 200384 B

__global__ __launch_bounds__(256, 1) void k_attn(const float* __restrict__ mix_logits)
{
    extern __shared__ float sm[];
    float* QiT  = sm + SM_QIT;
    float* KV   = sm + SM_KV;
    float* S    = sm + SM_S;
    float* E    = sm + SM_E;
    float* O    = sm + SM_O;
    float* den  = sm + SM_DEN;
    float* dred = sm + SM_DRED;
    float* mixs = sm + SM_MIX;

    const int t  = threadIdx.x;
    const int b  = blockIdx.y;
    const int i0 = blockIdx.x * 32;

    // head-mix softmax (deterministic eval mix)
    if (t < NH) {
        float m0 = mix_logits[t * 4 + 0], m1 = mix_logits[t * 4 + 1];
        float m2 = mix_logits[t * 4 + 2], m3 = mix_logits[t * 4 + 3];
        float mx = fmaxf(fmaxf(m0, m1), fmaxf(m2, m3));
        float e0 = __expf(m0 - mx), e1 = __expf(m1 - mx);
        float e2 = __expf(m2 - mx), e3 = __expf(m3 - mx);
        float inv = 1.f / (e0 + e1 + e2 + e3);
        mixs[t * 4 + 0] = e0 * inv; mixs[t * 4 + 1] = e1 * inv;
        mixs[t * 4 + 2] = e2 * inv; mixs[t * 4 + 3] = e3 * inv;
    }
    for (int e = t; e < 12 * 32 * 64 / 4; e += 256)
        reinterpret_cast<float4*>(O)[e] = make_float4(0.f, 0.f, 0.f, 0.f);
    for (int e = t; e < 12 * 32; e += 256) den[e] = 0.f;

    // load Q tile transposed: QiT[k][d][i]
    for (int e = t; e < 2048; e += 256) {
        int k  = e >> 9;
        int r  = (e >> 4) & 31;
        int c4 = (e & 15) << 2;
        float4 q = *reinterpret_cast<const float4*>(
            &g_QS[(((b * NG + k) << 10) + i0 + r) * HD + c4]);
        QiT[(k * 64 + c4 + 0) * 32 + r] = q.x;
        QiT[(k * 64 + c4 + 1) * 32 + r] = q.y;
        QiT[(k * 64 + c4 + 2) * 32 + r] = q.z;
        QiT[(k * 64 + c4 + 3) * 32 + r] = q.w;
    }
    __syncthreads();

    // thread mappings
    const int sk  = t >> 6;               // S: k head
    const int s64 = t & 63;
    const int si  = (s64 >> 3) << 2;      // S: i micro (4)
    const int sj  = (s64 & 7) << 2;       // S: j micro (4)

    const int eh  = (t & 127) >> 5;       // E: head-in-group
    const int ei  = t & 31;               // E: row
    const int ej0 = (t >> 7) << 4;        // E: j half (0/16)

    const int ph  = t >> 6;               // PV: head-in-group
    const int p64 = t & 63;
    const int pi  = (p64 >> 3) << 2;      // PV: i micro (4)
    const int pd  = (p64 & 7) << 3;       // PV: d micro (8)

    for (int jt = 0; jt < SEQ; jt += 32) {
        // K tile transposed into KV: KV[k][d][j]
        for (int e = t; e < 2048; e += 256) {
            int k  = e >> 9;
            int r  = (e >> 4) & 31;
            int c4 = (e & 15) << 2;
            float4 kv = *reinterpret_cast<const float4*>(
                &g_KS[(((b * NG + k) << 10) + jt + r) * HD + c4]);
            KV[(k * 64 + c4 + 0) * 32 + r] = kv.x;
            KV[(k * 64 + c4 + 1) * 32 + r] = kv.y;
            KV[(k * 64 + c4 + 2) * 32 + r] = kv.z;
            KV[(k * 64 + c4 + 3) * 32 + r] = kv.w;
        }
        __syncthreads();

        // S[k][i][j] = sum_d Q[i,d] K[j,d]
        {
            float acc[4][4];
#pragma unroll
            for (int i = 0; i < 4; i++)
#pragma unroll
                for (int j = 0; j < 4; j++) acc[i][j] = 0.f;
            const float* qp = QiT + sk * (64 * 32);
            const float* kp = KV + sk * (64 * 32);
#pragma unroll 8
            for (int d = 0; d < 64; d++) {
                float4 av = *reinterpret_cast<const float4*>(qp + d * 32 + si);
                float4 bv = *reinterpret_cast<const float4*>(kp + d * 32 + sj);
                float aa[4] = {av.x, av.y, av.z, av.w};
                float bb[4] = {bv.x, bv.y, bv.z, bv.w};
#pragma unroll
                for (int i = 0; i < 4; i++)
#pragma unroll
                    for (int j = 0; j < 4; j++)
                        acc[i][j] = fmaf(aa[i], bb[j], acc[i][j]);
            }
#pragma unroll
            for (int i = 0; i < 4; i++)
#pragma unroll
                for (int j = 0; j < 4; j++)
                    S[sk * 1056 + (si + i) * 33 + (sj + j)] = acc[i][j];
        }
        __syncthreads();

#pragma unroll 1
        for (int g = 0; g < 3; g++) {
            // V tile for heads 4g..4g+3 into KV (reused buffer): [hs][j][d]
            for (int e = t; e < 2048; e += 256) {
                int hs = e >> 9;
                int r  = (e >> 4) & 31;
                int c4 = (e & 15) << 2;
                float4 vv = *reinterpret_cast<const float4*>(
                    &g_VS[(((b * NH + g * 4 + hs) << 10) + jt + r) * HD + c4]);
                *reinterpret_cast<float4*>(&KV[(hs * 32 + r) * 64 + c4]) = vv;
            }
            // E = exp(mixed logits) — no max subtraction needed (|logit| small)
            {
                int h = g * 4 + eh;
                float m0 = mixs[h * 4 + 0], m1 = mixs[h * 4 + 1];
                float m2 = mixs[h * 4 + 2], m3 = mixs[h * 4 + 3];
                const float* s0 = S + 0 * 1056 + ei * 33;
                const float* s1 = S + 1 * 1056 + ei * 33;
                const float* s2 = S + 2 * 1056 + ei * 33;
                const float* s3 = S + 3 * 1056 + ei * 33;
                float* erow = E + eh * 1056 + ei * 33;
                float psum = 0.f;
#pragma unroll
                for (int j = ej0; j < ej0 + 16; j++) {
                    float l  = m0 * s0[j] + m1 * s1[j] + m2 * s2[j] + m3 * s3[j];
                    float ev = __expf(l);
                    erow[j] = ev;
                    psum += ev;
                }
                dred[t] = psum;
            }
            __syncthreads();
            if (t < 128)
                den[(g * 4 + (t >> 5)) * 32 + (t & 31)] += dred[t] + dred[t + 128];
            // PV: O[h] += E[h](32x32) @ V[h](32x64)
            {
                float acc[4][8];
#pragma unroll
                for (int i = 0; i < 4; i++)
#pragma unroll
                    for (int d = 0; d < 8; d++) acc[i][d] = 0.f;
                const float* ep = E + ph * 1056 + pi * 33;
                const float* vp = KV + ph * (32 * 64);
#pragma unroll 4
                for (int j = 0; j < 32; j++) {
                    float ee[4] = {ep[j], ep[33 + j], ep[66 + j], ep[99 + j]};
                    float4 v0 = *reinterpret_cast<const float4*>(vp + j * 64 + pd);
                    float4 v1 = *reinterpret_cast<const float4*>(vp + j * 64 + pd + 4);
                    float vv[8] = {v0.x, v0.y, v0.z, v0.w, v1.x, v1.y, v1.z, v1.w};
#pragma unroll
                    for (int i = 0; i < 4; i++)
#pragma unroll
                        for (int d = 0; d < 8; d++)
                            acc[i][d] = fmaf(ee[i], vv[d], acc[i][d]);
                }
                int h = g * 4 + ph;
#pragma unroll
                for (int i = 0; i < 4; i++) {
                    float4* op = reinterpret_cast<float4*>(&O[(h * 32 + pi + i) * 64 + pd]);
                    float4 o0 = op[0], o1 = op[1];
                    o0.x += acc[i][0]; o0.y += acc[i][1];
                    o0.z += acc[i][2]; o0.w += acc[i][3];
                    o1.x += acc[i][4]; o1.y += acc[i][5];
                    o1.z += acc[i][6]; o1.w += acc[i][7];
                    op[0] = o0; op[1] = o1;
                }
            }
            __syncthreads();
        }
    }

    // normalize and write AO[b][n][h*64+d]
    for (int e = t; e < 6144; e += 256) {
        int h  = e >> 9;
        int r  = (e >> 4) & 31;
        int c4 = (e & 15) << 2;
        float inv = 1.f / den[h * 32 + r];
        float4 o = *reinterpret_cast<const float4*>(&O[(h * 32 + r) * 64 + c4]);
        o.x *= inv; o.y *= inv; o.z *= inv; o.w *= inv;
        *reinterpret_cast<float4*>(
            &g_AO[((b << 10) + i0 + r) * DIMS + h * 64 + c4]) = o;
    }
}

// ---------------------------------------------------------------------------
extern "C" void kernel_launch(void* const* d_in, const int* in_sizes, int n_in,
                              void* d_out, int out_size)
{
    const float* x    = (const float*)d_in[0];
    const float* wqkv = (const float*)d_in[1];
    const float* mixl = (const float*)d_in[2];
    const float* wv   = (const float*)d_in[3];
    const float* wpr  = (const float*)d_in[4];
    const float* bpr  = (const float*)d_in[5];
    float* out = (float*)d_out;

    cudaFuncSetAttribute(k_attn, cudaFuncAttributeMaxDynamicSharedMemorySize,
                         SM_TOT * (int)sizeof(float));

    // K1: fused QK + V projections (8192 x 1280)
    k_sgemm<0><<<dim3(64, 10), 256>>>(x, wqkv, wv, nullptr, nullptr);
    // K2: fused flash attention with head mixing
    k_attn<<<dim3(32, 8), 256, SM_TOT * (int)sizeof(float)>>>(mixl);
    // K3: output projection + bias (8192 x 768)
    k_sgemm<1><<<dim3(64, 6), 256>>>(nullptr, wpr, nullptr, bpr, out);
}